// round 5
// baseline (speedup 1.0000x reference)
#include <cuda_runtime.h>

#define Bn 4
#define Tn 2048
#define Cn 768
#define Hn 12
#define Dn 64
#define Mrows (Bn * Tn)   // 8192
#define N_QKV (3 * Cn)    // 2304

// ---- scratch (no allocs allowed) ----
__device__ float g_q[Bn * Hn * Tn * Dn];
__device__ float g_k[Bn * Hn * Tn * Dn];
__device__ float g_v[Bn * Hn * Tn * Dn];
__device__ float g_att[Bn * Tn * Cn];

// ============================================================================
// Kernel 1: qkv = x @ w_qkv^T, fused RoPE on q/k, scatter to [b,h,t,d]
// 64x64 tile, BK=16, 256 threads, 4x4 micro-tile per thread. Static smem only.
// ============================================================================
__global__ __launch_bounds__(256) void qkv_rope_kernel(
    const float* __restrict__ x, const float* __restrict__ w,
    const float* __restrict__ rsin, const float* __restrict__ rcos)
{
    __shared__ float As[16][68];
    __shared__ float Bs[16][68];

    const int tid = threadIdx.x;
    const int tx = tid & 15;        // col group
    const int ty = tid >> 4;        // row group
    const int m0 = blockIdx.y * 64;
    const int n0 = blockIdx.x * 64;

    const int lrow = tid >> 2;      // 0..63
    const int lkv  = tid & 3;       // 0..3

    float acc[4][4];
    #pragma unroll
    for (int i = 0; i < 4; i++)
        #pragma unroll
        for (int j = 0; j < 4; j++) acc[i][j] = 0.f;

    for (int k0 = 0; k0 < Cn; k0 += 16) {
        float4 a = *(const float4*)&x[(m0 + lrow) * Cn + k0 + lkv * 4];
        float4 b = *(const float4*)&w[(n0 + lrow) * Cn + k0 + lkv * 4];
        As[lkv * 4 + 0][lrow] = a.x; As[lkv * 4 + 1][lrow] = a.y;
        As[lkv * 4 + 2][lrow] = a.z; As[lkv * 4 + 3][lrow] = a.w;
        Bs[lkv * 4 + 0][lrow] = b.x; Bs[lkv * 4 + 1][lrow] = b.y;
        Bs[lkv * 4 + 2][lrow] = b.z; Bs[lkv * 4 + 3][lrow] = b.w;
        __syncthreads();
        #pragma unroll
        for (int kk = 0; kk < 16; kk++) {
            float4 ra = *(const float4*)&As[kk][ty * 4];
            float4 rb = *(const float4*)&Bs[kk][tx * 4];
            acc[0][0] += ra.x * rb.x; acc[0][1] += ra.x * rb.y;
            acc[0][2] += ra.x * rb.z; acc[0][3] += ra.x * rb.w;
            acc[1][0] += ra.y * rb.x; acc[1][1] += ra.y * rb.y;
            acc[1][2] += ra.y * rb.z; acc[1][3] += ra.y * rb.w;
            acc[2][0] += ra.z * rb.x; acc[2][1] += ra.z * rb.y;
            acc[2][2] += ra.z * rb.z; acc[2][3] += ra.z * rb.w;
            acc[3][0] += ra.w * rb.x; acc[3][1] += ra.w * rb.y;
            acc[3][2] += ra.w * rb.z; acc[3][3] += ra.w * rb.w;
        }
        __syncthreads();
    }

    // epilogue: rope for q/k, scatter to [b,h,t,d]
    const int nbase = n0 + tx * 4;      // aligned to 4; 4 cols stay in one head
    const int s   = nbase / Cn;         // 0=q 1=k 2=v
    const int rem = nbase % Cn;
    const int h   = rem / Dn;
    const int d0  = rem % Dn;           // aligned to 4

    #pragma unroll
    for (int i = 0; i < 4; i++) {
        const int m = m0 + ty * 4 + i;
        const int bb = m / Tn, t = m % Tn;
        const int base = ((bb * Hn + h) * Tn + t) * Dn + d0;
        float v0 = acc[i][0], v1 = acc[i][1], v2 = acc[i][2], v3 = acc[i][3];
        if (s == 2) {
            g_v[base + 0] = v0; g_v[base + 1] = v1;
            g_v[base + 2] = v2; g_v[base + 3] = v3;
        } else {
            const int i0 = d0 >> 1;   // freq index of first pair
            float s0 = rsin[t * (Dn / 2) + i0],     c0 = rcos[t * (Dn / 2) + i0];
            float s1 = rsin[t * (Dn / 2) + i0 + 1], c1 = rcos[t * (Dn / 2) + i0 + 1];
            float o0 = v0 * c0 - v1 * s0;
            float o1 = v0 * s0 + v1 * c0;
            float o2 = v2 * c1 - v3 * s1;
            float o3 = v2 * s1 + v3 * c1;
            float* dst = (s == 0) ? g_q : g_k;
            dst[base + 0] = o0; dst[base + 1] = o1;
            dst[base + 2] = o2; dst[base + 3] = o3;
        }
    }
}

// ============================================================================
// Kernel 2: causal flash attention. 128 q-rows per block (1 per thread).
// Q row and scores in REGISTERS; KV tiles of 32 rows in STATIC smem (16 KB).
// Next KV tile is prefetched into registers during current tile's compute.
// No dynamic smem, no cudaFuncSetAttribute. Causal tile skipping.
// ============================================================================
__global__ __launch_bounds__(128) void attn_kernel()
{
    __shared__ float Ks[32 * 64];
    __shared__ float Vs[32 * 64];

    const int tid = threadIdx.x;
    const int qb = blockIdx.x;
    const int bh = blockIdx.y;
    const int q0 = qb * 128;

    const float* __restrict__ qptr = g_q + (size_t)bh * Tn * Dn;
    const float* __restrict__ kptr = g_k + (size_t)bh * Tn * Dn;
    const float* __restrict__ vptr = g_v + (size_t)bh * Tn * Dn;

    // per-thread slice of the 32x64 tile loads: 4 float4 of K, 4 of V
    const int lr = tid >> 2;              // 0..31 (row)
    const int lc = (tid & 3) * 4;         // 0,4,8,12 (col group start, x4 floats)
    // each thread loads cols [lc*?]: we cover 16 float4/row with 4 threads,
    // rows stride 32 over 32 rows -> thread handles row lr, float4 cols lc..lc+3 step 4? No:
    // 32 rows * 16 float4 = 512 float4; 128 threads -> 4 each.
    // Layout: thread i handles elements i, i+128, i+256, i+384 of the flat index.

    // Q row -> registers, pre-scaled by 1/sqrt(D)
    const float scale = 0.125f;   // 1/sqrt(64)
    float4 qreg[16];
    {
        const float4* qrow = (const float4*)&qptr[(size_t)(q0 + tid) * Dn];
        #pragma unroll
        for (int i = 0; i < 16; i++) {
            float4 qv = qrow[i];
            qv.x *= scale; qv.y *= scale; qv.z *= scale; qv.w *= scale;
            qreg[i] = qv;
        }
    }

    const int t_q = q0 + tid;
    float m_run = -1e30f, l_run = 0.f;
    float accd[64];
    #pragma unroll
    for (int d = 0; d < 64; d++) accd[d] = 0.f;

    const int ntiles = (q0 + 128) / 32;   // causal skip

    // prefetch tile 0 into registers
    float4 kpre[4], vpre[4];
    #pragma unroll
    for (int u = 0; u < 4; u++) {
        const int idx = tid + u * 128;            // flat float4 index in tile
        const int r = idx >> 4, c = (idx & 15) * 4;
        kpre[u] = *(const float4*)&kptr[r * Dn + c];
        vpre[u] = *(const float4*)&vptr[r * Dn + c];
    }

    for (int kt = 0; kt < ntiles; kt++) {
        __syncthreads();   // protect Ks/Vs reuse across iterations
        // commit prefetched tile to smem
        #pragma unroll
        for (int u = 0; u < 4; u++) {
            const int idx = tid + u * 128;
            const int r = idx >> 4, c = (idx & 15) * 4;
            *(float4*)&Ks[r * 64 + c] = kpre[u];
            *(float4*)&Vs[r * 64 + c] = vpre[u];
        }
        __syncthreads();

        // prefetch next tile while computing this one
        if (kt + 1 < ntiles) {
            const int nbase = (kt + 1) * 32;
            #pragma unroll
            for (int u = 0; u < 4; u++) {
                const int idx = tid + u * 128;
                const int r = idx >> 4, c = (idx & 15) * 4;
                kpre[u] = *(const float4*)&kptr[(nbase + r) * Dn + c];
                vpre[u] = *(const float4*)&vptr[(nbase + r) * Dn + c];
            }
        }

        const int kbase = kt * 32;

        // --- scores in registers (Q regs x K broadcast from smem) ---
        float sreg[32];
        float tmax = -1e30f;
        #pragma unroll
        for (int j = 0; j < 32; j += 4) {
            float s0 = 0.f, s1 = 0.f, s2 = 0.f, s3 = 0.f;
            #pragma unroll
            for (int dq = 0; dq < 16; dq++) {
                const int d = dq * 4;
                float4 qv = qreg[dq];
                float4 k0 = *(const float4*)&Ks[(j + 0) * 64 + d];
                float4 k1 = *(const float4*)&Ks[(j + 1) * 64 + d];
                float4 k2 = *(const float4*)&Ks[(j + 2) * 64 + d];
                float4 k3 = *(const float4*)&Ks[(j + 3) * 64 + d];
                s0 += qv.x * k0.x + qv.y * k0.y + qv.z * k0.z + qv.w * k0.w;
                s1 += qv.x * k1.x + qv.y * k1.y + qv.z * k1.z + qv.w * k1.w;
                s2 += qv.x * k2.x + qv.y * k2.y + qv.z * k2.z + qv.w * k2.w;
                s3 += qv.x * k3.x + qv.y * k3.y + qv.z * k3.z + qv.w * k3.w;
            }
            if (kbase + j + 0 > t_q) s0 = -1e30f;
            if (kbase + j + 1 > t_q) s1 = -1e30f;
            if (kbase + j + 2 > t_q) s2 = -1e30f;
            if (kbase + j + 3 > t_q) s3 = -1e30f;
            sreg[j + 0] = s0; sreg[j + 1] = s1;
            sreg[j + 2] = s2; sreg[j + 3] = s3;
            tmax = fmaxf(tmax, fmaxf(fmaxf(s0, s1), fmaxf(s2, s3)));
        }

        // --- online softmax update ---
        const float m_new = fmaxf(m_run, tmax);
        const float corr = __expf(m_run - m_new);
        l_run *= corr;
        #pragma unroll
        for (int d = 0; d < 64; d++) accd[d] *= corr;
        m_run = m_new;

        float lsum = 0.f;
        #pragma unroll
        for (int j = 0; j < 32; j += 4) {
            float p0 = __expf(sreg[j + 0] - m_new);
            float p1 = __expf(sreg[j + 1] - m_new);
            float p2 = __expf(sreg[j + 2] - m_new);
            float p3 = __expf(sreg[j + 3] - m_new);
            lsum += (p0 + p1) + (p2 + p3);
            #pragma unroll
            for (int d = 0; d < 64; d += 4) {
                float4 v0 = *(const float4*)&Vs[(j + 0) * 64 + d];
                float4 v1 = *(const float4*)&Vs[(j + 1) * 64 + d];
                float4 v2 = *(const float4*)&Vs[(j + 2) * 64 + d];
                float4 v3 = *(const float4*)&Vs[(j + 3) * 64 + d];
                accd[d + 0] += p0 * v0.x + p1 * v1.x + p2 * v2.x + p3 * v3.x;
                accd[d + 1] += p0 * v0.y + p1 * v1.y + p2 * v2.y + p3 * v3.y;
                accd[d + 2] += p0 * v0.z + p1 * v1.z + p2 * v2.z + p3 * v3.z;
                accd[d + 3] += p0 * v0.w + p1 * v1.w + p2 * v2.w + p3 * v3.w;
            }
        }
        l_run += lsum;
    }

    const float inv = 1.f / l_run;
    const int bb = bh / Hn, h = bh % Hn;
    float* outp = g_att + ((size_t)(bb * Tn + t_q)) * Cn + h * Dn;
    #pragma unroll
    for (int d = 0; d < 64; d += 4) {
        float4 o;
        o.x = accd[d + 0] * inv; o.y = accd[d + 1] * inv;
        o.z = accd[d + 2] * inv; o.w = accd[d + 3] * inv;
        *(float4*)&outp[d] = o;
    }
}

// ============================================================================
// Kernel 3: out = g_att @ w_proj^T
// ============================================================================
__global__ __launch_bounds__(256) void proj_kernel(
    const float* __restrict__ wp, float* __restrict__ out)
{
    __shared__ float As[16][68];
    __shared__ float Bs[16][68];

    const int tid = threadIdx.x;
    const int tx = tid & 15;
    const int ty = tid >> 4;
    const int m0 = blockIdx.y * 64;
    const int n0 = blockIdx.x * 64;

    const int lrow = tid >> 2;
    const int lkv  = tid & 3;

    float acc[4][4];
    #pragma unroll
    for (int i = 0; i < 4; i++)
        #pragma unroll
        for (int j = 0; j < 4; j++) acc[i][j] = 0.f;

    for (int k0 = 0; k0 < Cn; k0 += 16) {
        float4 a = *(const float4*)&g_att[(m0 + lrow) * Cn + k0 + lkv * 4];
        float4 b = *(const float4*)&wp[(n0 + lrow) * Cn + k0 + lkv * 4];
        As[lkv * 4 + 0][lrow] = a.x; As[lkv * 4 + 1][lrow] = a.y;
        As[lkv * 4 + 2][lrow] = a.z; As[lkv * 4 + 3][lrow] = a.w;
        Bs[lkv * 4 + 0][lrow] = b.x; Bs[lkv * 4 + 1][lrow] = b.y;
        Bs[lkv * 4 + 2][lrow] = b.z; Bs[lkv * 4 + 3][lrow] = b.w;
        __syncthreads();
        #pragma unroll
        for (int kk = 0; kk < 16; kk++) {
            float4 ra = *(const float4*)&As[kk][ty * 4];
            float4 rb = *(const float4*)&Bs[kk][tx * 4];
            acc[0][0] += ra.x * rb.x; acc[0][1] += ra.x * rb.y;
            acc[0][2] += ra.x * rb.z; acc[0][3] += ra.x * rb.w;
            acc[1][0] += ra.y * rb.x; acc[1][1] += ra.y * rb.y;
            acc[1][2] += ra.y * rb.z; acc[1][3] += ra.y * rb.w;
            acc[2][0] += ra.z * rb.x; acc[2][1] += ra.z * rb.y;
            acc[2][2] += ra.z * rb.z; acc[2][3] += ra.z * rb.w;
            acc[3][0] += ra.w * rb.x; acc[3][1] += ra.w * rb.y;
            acc[3][2] += ra.w * rb.z; acc[3][3] += ra.w * rb.w;
        }
        __syncthreads();
    }

    #pragma unroll
    for (int i = 0; i < 4; i++) {
        const int m = m0 + ty * 4 + i;
        const int n = n0 + tx * 4;
        float4 o;
        o.x = acc[i][0]; o.y = acc[i][1]; o.z = acc[i][2]; o.w = acc[i][3];
        *(float4*)&out[m * Cn + n] = o;
    }
}

// ============================================================================
extern "C" void kernel_launch(void* const* d_in, const int* in_sizes, int n_in,
                              void* d_out, int out_size)
{
    const float* x      = (const float*)d_in[0];
    const float* w_qkv  = (const float*)d_in[1];
    const float* w_proj = (const float*)d_in[2];
    const float* r_sin  = (const float*)d_in[3];
    const float* r_cos  = (const float*)d_in[4];
    float* out = (float*)d_out;

    // kernel 1: qkv + rope
    {
        dim3 grid(N_QKV / 64, Mrows / 64);
        qkv_rope_kernel<<<grid, 256>>>(x, w_qkv, r_sin, r_cos);
    }

    // kernel 2: attention (static smem only — no attribute calls)
    {
        dim3 grid(Tn / 128, Bn * Hn);
        attn_kernel<<<grid, 128>>>();
    }

    // kernel 3: output projection
    {
        dim3 grid(Cn / 64, Mrows / 64);
        proj_kernel<<<grid, 256>>>(w_proj, out);
    }
}

// round 11
// speedup vs baseline: 1.4952x; 1.4952x over previous
#include <cuda_runtime.h>

#define Bn 4
#define Tn 2048
#define Cn 768
#define Hn 12
#define Dn 64
#define Mrows (Bn * Tn)   // 8192
#define N_QKV (3 * Cn)    // 2304

// ---- scratch (no allocs allowed) ----
__device__ float g_q[Bn * Hn * Tn * Dn];
__device__ float g_k[Bn * Hn * Tn * Dn];
__device__ float g_v[Bn * Hn * Tn * Dn];
__device__ float g_att[Bn * Tn * Cn];

#define SMP 132   // smem row stride: multiple of 4 floats -> 16B-aligned rows for LDS.128

// ---- packed fp32x2 helpers (sm_103a FFMA2 path; bit-exact per lane) ----
typedef unsigned long long u64t;
__device__ __forceinline__ u64t fma2(u64t a, u64t b, u64t c) {
    u64t r; asm("fma.rn.f32x2 %0, %1, %2, %3;" : "=l"(r) : "l"(a), "l"(b), "l"(c)); return r;
}
__device__ __forceinline__ u64t mul2(u64t a, u64t b) {
    u64t r; asm("mul.rn.f32x2 %0, %1, %2;" : "=l"(r) : "l"(a), "l"(b)); return r;
}
__device__ __forceinline__ u64t pack2(float lo, float hi) {
    u64t r; asm("mov.b64 %0, {%1, %2};" : "=l"(r) : "f"(lo), "f"(hi)); return r;
}
__device__ __forceinline__ float2 unpack2(u64t v) {
    float lo, hi; asm("mov.b64 {%0, %1}, %2;" : "=f"(lo), "=f"(hi) : "l"(v));
    return make_float2(lo, hi);
}

// ============================================================================
// Kernel 1: qkv = x @ w_qkv^T, fused RoPE, scatter to [b,h,t,d]
// 128x128x16 block tile, 256 threads, 8x8 micro-tile (16 FMA per LDS.128).
// ============================================================================
__global__ __launch_bounds__(256) void qkv_rope_kernel(
    const float* __restrict__ x, const float* __restrict__ w,
    const float* __restrict__ rsin, const float* __restrict__ rcos)
{
    __shared__ float As[16][SMP];
    __shared__ float Bs[16][SMP];

    const int tid = threadIdx.x;
    const int tx = tid & 15;
    const int ty = tid >> 4;
    const int m0 = blockIdx.y * 128;
    const int n0 = blockIdx.x * 128;

    float acc[8][8];
    #pragma unroll
    for (int i = 0; i < 8; i++)
        #pragma unroll
        for (int j = 0; j < 8; j++) acc[i][j] = 0.f;

    for (int k0 = 0; k0 < Cn; k0 += 16) {
        #pragma unroll
        for (int u = 0; u < 2; u++) {
            const int idx = tid + u * 256;
            const int r = idx >> 2, c4 = (idx & 3) * 4;
            float4 a = *(const float4*)&x[(m0 + r) * Cn + k0 + c4];
            float4 b = *(const float4*)&w[(n0 + r) * Cn + k0 + c4];
            As[c4 + 0][r] = a.x; As[c4 + 1][r] = a.y;
            As[c4 + 2][r] = a.z; As[c4 + 3][r] = a.w;
            Bs[c4 + 0][r] = b.x; Bs[c4 + 1][r] = b.y;
            Bs[c4 + 2][r] = b.z; Bs[c4 + 3][r] = b.w;
        }
        __syncthreads();
        #pragma unroll
        for (int kk = 0; kk < 16; kk++) {
            float4 a0 = *(const float4*)&As[kk][ty * 8];
            float4 a1 = *(const float4*)&As[kk][ty * 8 + 4];
            float4 b0 = *(const float4*)&Bs[kk][tx * 8];
            float4 b1 = *(const float4*)&Bs[kk][tx * 8 + 4];
            float ar[8] = {a0.x, a0.y, a0.z, a0.w, a1.x, a1.y, a1.z, a1.w};
            float br[8] = {b0.x, b0.y, b0.z, b0.w, b1.x, b1.y, b1.z, b1.w};
            #pragma unroll
            for (int i = 0; i < 8; i++)
                #pragma unroll
                for (int j = 0; j < 8; j++)
                    acc[i][j] += ar[i] * br[j];
        }
        __syncthreads();
    }

    const int nbase = n0 + tx * 8;
    const int s   = nbase / Cn;
    const int rem = nbase % Cn;
    const int h   = rem / Dn;
    const int d0  = rem % Dn;

    #pragma unroll
    for (int i = 0; i < 8; i++) {
        const int m = m0 + ty * 8 + i;
        const int bb = m / Tn, t = m % Tn;
        float* __restrict__ dst;
        float o[8];
        if (s == 2) {
            dst = g_v;
            #pragma unroll
            for (int j = 0; j < 8; j++) o[j] = acc[i][j];
        } else {
            dst = (s == 0) ? g_q : g_k;
            const int i0 = d0 >> 1;
            #pragma unroll
            for (int p = 0; p < 4; p++) {
                float sp = rsin[t * (Dn / 2) + i0 + p];
                float cp = rcos[t * (Dn / 2) + i0 + p];
                float e = acc[i][2 * p], f = acc[i][2 * p + 1];
                o[2 * p]     = e * cp - f * sp;
                o[2 * p + 1] = e * sp + f * cp;
            }
        }
        const int base = ((bb * Hn + h) * Tn + t) * Dn + d0;
        float4 w0, w1;
        w0.x = o[0]; w0.y = o[1]; w0.z = o[2]; w0.w = o[3];
        w1.x = o[4]; w1.y = o[5]; w1.z = o[6]; w1.w = o[7];
        *(float4*)&dst[base]     = w0;
        *(float4*)&dst[base + 4] = w1;
    }
}

// ============================================================================
// Kernel 2: causal flash attention, packed f32x2 math (FFMA2).
// 128 q-rows/block (1/thread), 32-row KV tiles in static smem, reg prefetch,
// causal tile skipping. Q and accumulators held as packed f32x2 pairs.
// ============================================================================
__global__ __launch_bounds__(128) void attn_kernel()
{
    __shared__ float Ks[32 * 64];
    __shared__ float Vs[32 * 64];

    const int tid = threadIdx.x;
    const int qb = blockIdx.x;
    const int bh = blockIdx.y;
    const int q0 = qb * 128;

    const float* __restrict__ qptr = g_q + (size_t)bh * Tn * Dn;
    const float* __restrict__ kptr = g_k + (size_t)bh * Tn * Dn;
    const float* __restrict__ vptr = g_v + (size_t)bh * Tn * Dn;

    // Q row -> 32 packed pairs, pre-scaled by 1/sqrt(D)
    u64t qp[32];
    {
        const u64t sc2 = pack2(0.125f, 0.125f);
        const ulonglong2* qrow = (const ulonglong2*)&qptr[(size_t)(q0 + tid) * Dn];
        #pragma unroll
        for (int i = 0; i < 16; i++) {
            ulonglong2 qq = qrow[i];
            qp[2 * i + 0] = mul2(qq.x, sc2);
            qp[2 * i + 1] = mul2(qq.y, sc2);
        }
    }

    const int t_q = q0 + tid;
    float m_run = -1e30f, l_run = 0.f;
    u64t accp[32];
    #pragma unroll
    for (int i = 0; i < 32; i++) accp[i] = 0ull;   // (0.0f, 0.0f)

    const int ntiles = (q0 + 128) / 32;   // causal skip

    float4 kpre[4], vpre[4];
    #pragma unroll
    for (int u = 0; u < 4; u++) {
        const int idx = tid + u * 128;
        const int r = idx >> 4, c = (idx & 15) * 4;
        kpre[u] = *(const float4*)&kptr[r * Dn + c];
        vpre[u] = *(const float4*)&vptr[r * Dn + c];
    }

    for (int kt = 0; kt < ntiles; kt++) {
        __syncthreads();
        #pragma unroll
        for (int u = 0; u < 4; u++) {
            const int idx = tid + u * 128;
            const int r = idx >> 4, c = (idx & 15) * 4;
            *(float4*)&Ks[r * 64 + c] = kpre[u];
            *(float4*)&Vs[r * 64 + c] = vpre[u];
        }
        __syncthreads();

        if (kt + 1 < ntiles) {
            const int nb = (kt + 1) * 32;
            #pragma unroll
            for (int u = 0; u < 4; u++) {
                const int idx = tid + u * 128;
                const int r = idx >> 4, c = (idx & 15) * 4;
                kpre[u] = *(const float4*)&kptr[(nb + r) * Dn + c];
                vpre[u] = *(const float4*)&vptr[(nb + r) * Dn + c];
            }
        }

        const int kbase = kt * 32;

        // --- scores: packed dot products ---
        float sreg[32];
        float tmax = -1e30f;
        #pragma unroll
        for (int j = 0; j < 32; j += 4) {
            u64t a0 = 0ull, a1 = 0ull, a2 = 0ull, a3 = 0ull;
            #pragma unroll
            for (int d = 0; d < 64; d += 4) {
                const int pi = d >> 1;
                ulonglong2 k0 = *(const ulonglong2*)&Ks[(j + 0) * 64 + d];
                ulonglong2 k1 = *(const ulonglong2*)&Ks[(j + 1) * 64 + d];
                ulonglong2 k2 = *(const ulonglong2*)&Ks[(j + 2) * 64 + d];
                ulonglong2 k3 = *(const ulonglong2*)&Ks[(j + 3) * 64 + d];
                a0 = fma2(qp[pi], k0.x, a0); a0 = fma2(qp[pi + 1], k0.y, a0);
                a1 = fma2(qp[pi], k1.x, a1); a1 = fma2(qp[pi + 1], k1.y, a1);
                a2 = fma2(qp[pi], k2.x, a2); a2 = fma2(qp[pi + 1], k2.y, a2);
                a3 = fma2(qp[pi], k3.x, a3); a3 = fma2(qp[pi + 1], k3.y, a3);
            }
            float2 f0 = unpack2(a0), f1 = unpack2(a1), f2 = unpack2(a2), f3 = unpack2(a3);
            float s0 = f0.x + f0.y, s1 = f1.x + f1.y, s2 = f2.x + f2.y, s3 = f3.x + f3.y;
            if (kbase + j + 0 > t_q) s0 = -1e30f;
            if (kbase + j + 1 > t_q) s1 = -1e30f;
            if (kbase + j + 2 > t_q) s2 = -1e30f;
            if (kbase + j + 3 > t_q) s3 = -1e30f;
            sreg[j + 0] = s0; sreg[j + 1] = s1;
            sreg[j + 2] = s2; sreg[j + 3] = s3;
            tmax = fmaxf(tmax, fmaxf(fmaxf(s0, s1), fmaxf(s2, s3)));
        }

        // --- online softmax update ---
        const float m_new = fmaxf(m_run, tmax);
        const float corr = __expf(m_run - m_new);
        const u64t corr2 = pack2(corr, corr);
        l_run *= corr;
        #pragma unroll
        for (int i = 0; i < 32; i++) accp[i] = mul2(accp[i], corr2);
        m_run = m_new;

        float lsum = 0.f;
        #pragma unroll
        for (int j = 0; j < 32; j += 4) {
            float p0 = __expf(sreg[j + 0] - m_new);
            float p1 = __expf(sreg[j + 1] - m_new);
            float p2 = __expf(sreg[j + 2] - m_new);
            float p3 = __expf(sreg[j + 3] - m_new);
            lsum += (p0 + p1) + (p2 + p3);
            const u64t pj0 = pack2(p0, p0), pj1 = pack2(p1, p1);
            const u64t pj2 = pack2(p2, p2), pj3 = pack2(p3, p3);
            #pragma unroll
            for (int d = 0; d < 64; d += 4) {
                const int pi = d >> 1;
                ulonglong2 v0 = *(const ulonglong2*)&Vs[(j + 0) * 64 + d];
                ulonglong2 v1 = *(const ulonglong2*)&Vs[(j + 1) * 64 + d];
                ulonglong2 v2 = *(const ulonglong2*)&Vs[(j + 2) * 64 + d];
                ulonglong2 v3 = *(const ulonglong2*)&Vs[(j + 3) * 64 + d];
                accp[pi]     = fma2(pj3, v3.x, fma2(pj2, v2.x, fma2(pj1, v1.x, fma2(pj0, v0.x, accp[pi]))));
                accp[pi + 1] = fma2(pj3, v3.y, fma2(pj2, v2.y, fma2(pj1, v1.y, fma2(pj0, v0.y, accp[pi + 1]))));
            }
        }
        l_run += lsum;
    }

    const float inv = 1.f / l_run;
    const u64t inv2 = pack2(inv, inv);
    const int bb = bh / Hn, h = bh % Hn;
    float* outp = g_att + ((size_t)(bb * Tn + t_q)) * Cn + h * Dn;
    #pragma unroll
    for (int i = 0; i < 32; i += 2) {
        ulonglong2 o;
        o.x = mul2(accp[i],     inv2);
        o.y = mul2(accp[i + 1], inv2);
        *(ulonglong2*)&outp[i * 2] = o;
    }
}

// ============================================================================
// Kernel 3: out = g_att @ w_proj^T — same 128x128x16 / 8x8 scheme
// ============================================================================
__global__ __launch_bounds__(256) void proj_kernel(
    const float* __restrict__ wp, float* __restrict__ out)
{
    __shared__ float As[16][SMP];
    __shared__ float Bs[16][SMP];

    const int tid = threadIdx.x;
    const int tx = tid & 15;
    const int ty = tid >> 4;
    const int m0 = blockIdx.y * 128;
    const int n0 = blockIdx.x * 128;

    float acc[8][8];
    #pragma unroll
    for (int i = 0; i < 8; i++)
        #pragma unroll
        for (int j = 0; j < 8; j++) acc[i][j] = 0.f;

    for (int k0 = 0; k0 < Cn; k0 += 16) {
        #pragma unroll
        for (int u = 0; u < 2; u++) {
            const int idx = tid + u * 256;
            const int r = idx >> 2, c4 = (idx & 3) * 4;
            float4 a = *(const float4*)&g_att[(m0 + r) * Cn + k0 + c4];
            float4 b = *(const float4*)&wp[(n0 + r) * Cn + k0 + c4];
            As[c4 + 0][r] = a.x; As[c4 + 1][r] = a.y;
            As[c4 + 2][r] = a.z; As[c4 + 3][r] = a.w;
            Bs[c4 + 0][r] = b.x; Bs[c4 + 1][r] = b.y;
            Bs[c4 + 2][r] = b.z; Bs[c4 + 3][r] = b.w;
        }
        __syncthreads();
        #pragma unroll
        for (int kk = 0; kk < 16; kk++) {
            float4 a0 = *(const float4*)&As[kk][ty * 8];
            float4 a1 = *(const float4*)&As[kk][ty * 8 + 4];
            float4 b0 = *(const float4*)&Bs[kk][tx * 8];
            float4 b1 = *(const float4*)&Bs[kk][tx * 8 + 4];
            float ar[8] = {a0.x, a0.y, a0.z, a0.w, a1.x, a1.y, a1.z, a1.w};
            float br[8] = {b0.x, b0.y, b0.z, b0.w, b1.x, b1.y, b1.z, b1.w};
            #pragma unroll
            for (int i = 0; i < 8; i++)
                #pragma unroll
                for (int j = 0; j < 8; j++)
                    acc[i][j] += ar[i] * br[j];
        }
        __syncthreads();
    }

    #pragma unroll
    for (int i = 0; i < 8; i++) {
        const int m = m0 + ty * 8 + i;
        const int n = n0 + tx * 8;
        float4 w0, w1;
        w0.x = acc[i][0]; w0.y = acc[i][1]; w0.z = acc[i][2]; w0.w = acc[i][3];
        w1.x = acc[i][4]; w1.y = acc[i][5]; w1.z = acc[i][6]; w1.w = acc[i][7];
        *(float4*)&out[m * Cn + n]     = w0;
        *(float4*)&out[m * Cn + n + 4] = w1;
    }
}

// ============================================================================
extern "C" void kernel_launch(void* const* d_in, const int* in_sizes, int n_in,
                              void* d_out, int out_size)
{
    const float* x      = (const float*)d_in[0];
    const float* w_qkv  = (const float*)d_in[1];
    const float* w_proj = (const float*)d_in[2];
    const float* r_sin  = (const float*)d_in[3];
    const float* r_cos  = (const float*)d_in[4];
    float* out = (float*)d_out;

    // kernel 1: qkv + rope
    {
        dim3 grid(N_QKV / 128, Mrows / 128);
        qkv_rope_kernel<<<grid, 256>>>(x, w_qkv, r_sin, r_cos);
    }

    // kernel 2: attention (packed f32x2)
    {
        dim3 grid(Tn / 128, Bn * Hn);
        attn_kernel<<<grid, 128>>>();
    }

    // kernel 3: output projection
    {
        dim3 grid(Cn / 128, Mrows / 128);
        proj_kernel<<<grid, 256>>>(w_proj, out);
    }
}

// round 13
// speedup vs baseline: 1.5023x; 1.0048x over previous
#include <cuda_runtime.h>
#include <cstdint>

#define Bn 4
#define Tn 2048
#define Cn 768
#define Hn 12
#define Dn 64
#define Mrows (Bn * Tn)   // 8192
#define N_QKV (3 * Cn)    // 2304

// ---- scratch (no allocs allowed) ----
__device__ float g_q[Bn * Hn * Tn * Dn];
__device__ float g_k[Bn * Hn * Tn * Dn];
__device__ float g_v[Bn * Hn * Tn * Dn];
__device__ float g_att[Bn * Tn * Cn];

#define SMP 132   // smem row stride: multiple of 4 floats -> 16B-aligned rows for LDS.128

// ---- packed fp32x2 helpers (sm_103a FFMA2 path; bit-exact per lane) ----
typedef unsigned long long u64t;
__device__ __forceinline__ u64t fma2(u64t a, u64t b, u64t c) {
    u64t r; asm("fma.rn.f32x2 %0, %1, %2, %3;" : "=l"(r) : "l"(a), "l"(b), "l"(c)); return r;
}
__device__ __forceinline__ u64t mul2(u64t a, u64t b) {
    u64t r; asm("mul.rn.f32x2 %0, %1, %2;" : "=l"(r) : "l"(a), "l"(b)); return r;
}
__device__ __forceinline__ u64t pack2(float lo, float hi) {
    u64t r; asm("mov.b64 %0, {%1, %2};" : "=l"(r) : "f"(lo), "f"(hi)); return r;
}
__device__ __forceinline__ float2 unpack2(u64t v) {
    float lo, hi; asm("mov.b64 {%0, %1}, %2;" : "=f"(lo), "=f"(hi) : "l"(v));
    return make_float2(lo, hi);
}

// ---- cp.async helpers (16B, L1-bypass) ----
__device__ __forceinline__ void cpa16(uint32_t saddr, const void* gaddr) {
    asm volatile("cp.async.cg.shared.global [%0], [%1], 16;" :: "r"(saddr), "l"(gaddr));
}
__device__ __forceinline__ void cpa_commit() {
    asm volatile("cp.async.commit_group;");
}
__device__ __forceinline__ void cpa_wait1() {
    asm volatile("cp.async.wait_group 1;");
}
__device__ __forceinline__ void cpa_wait0() {
    asm volatile("cp.async.wait_group 0;");
}

// ============================================================================
// Kernel 1: qkv = x @ w_qkv^T, fused RoPE, scatter to [b,h,t,d]
// 128x128x16 tile, 256 threads, 8x8 micro-tile on packed f32x2 (32 FFMA2/kk).
// ============================================================================
__global__ __launch_bounds__(256) void qkv_rope_kernel(
    const float* __restrict__ x, const float* __restrict__ w,
    const float* __restrict__ rsin, const float* __restrict__ rcos)
{
    __shared__ float As[16][SMP];
    __shared__ float Bs[16][SMP];

    const int tid = threadIdx.x;
    const int tx = tid & 15;
    const int ty = tid >> 4;
    const int m0 = blockIdx.y * 128;
    const int n0 = blockIdx.x * 128;

    u64t accp[8][4];
    #pragma unroll
    for (int i = 0; i < 8; i++)
        #pragma unroll
        for (int j = 0; j < 4; j++) accp[i][j] = 0ull;

    for (int k0 = 0; k0 < Cn; k0 += 16) {
        #pragma unroll
        for (int u = 0; u < 2; u++) {
            const int idx = tid + u * 256;
            const int r = idx >> 2, c4 = (idx & 3) * 4;
            float4 a = *(const float4*)&x[(m0 + r) * Cn + k0 + c4];
            float4 b = *(const float4*)&w[(n0 + r) * Cn + k0 + c4];
            As[c4 + 0][r] = a.x; As[c4 + 1][r] = a.y;
            As[c4 + 2][r] = a.z; As[c4 + 3][r] = a.w;
            Bs[c4 + 0][r] = b.x; Bs[c4 + 1][r] = b.y;
            Bs[c4 + 2][r] = b.z; Bs[c4 + 3][r] = b.w;
        }
        __syncthreads();
        #pragma unroll
        for (int kk = 0; kk < 16; kk++) {
            float4 a0 = *(const float4*)&As[kk][ty * 8];
            float4 a1 = *(const float4*)&As[kk][ty * 8 + 4];
            ulonglong2 b01 = *(const ulonglong2*)&Bs[kk][tx * 8];
            ulonglong2 b23 = *(const ulonglong2*)&Bs[kk][tx * 8 + 4];
            const u64t bp0 = b01.x, bp1 = b01.y, bp2 = b23.x, bp3 = b23.y;
            float ar[8] = {a0.x, a0.y, a0.z, a0.w, a1.x, a1.y, a1.z, a1.w};
            #pragma unroll
            for (int i = 0; i < 8; i++) {
                const u64t ai = pack2(ar[i], ar[i]);
                accp[i][0] = fma2(ai, bp0, accp[i][0]);
                accp[i][1] = fma2(ai, bp1, accp[i][1]);
                accp[i][2] = fma2(ai, bp2, accp[i][2]);
                accp[i][3] = fma2(ai, bp3, accp[i][3]);
            }
        }
        __syncthreads();
    }

    const int nbase = n0 + tx * 8;
    const int s   = nbase / Cn;
    const int rem = nbase % Cn;
    const int h   = rem / Dn;
    const int d0  = rem % Dn;

    #pragma unroll
    for (int i = 0; i < 8; i++) {
        const int m = m0 + ty * 8 + i;
        const int bb = m / Tn, t = m % Tn;
        float2 p0 = unpack2(accp[i][0]), p1 = unpack2(accp[i][1]);
        float2 p2 = unpack2(accp[i][2]), p3 = unpack2(accp[i][3]);
        float acc8[8] = {p0.x, p0.y, p1.x, p1.y, p2.x, p2.y, p3.x, p3.y};
        float* __restrict__ dst;
        float o[8];
        if (s == 2) {
            dst = g_v;
            #pragma unroll
            for (int j = 0; j < 8; j++) o[j] = acc8[j];
        } else {
            dst = (s == 0) ? g_q : g_k;
            const int i0 = d0 >> 1;
            #pragma unroll
            for (int p = 0; p < 4; p++) {
                float sp = rsin[t * (Dn / 2) + i0 + p];
                float cp = rcos[t * (Dn / 2) + i0 + p];
                float e = acc8[2 * p], f = acc8[2 * p + 1];
                o[2 * p]     = e * cp - f * sp;
                o[2 * p + 1] = e * sp + f * cp;
            }
        }
        const int base = ((bb * Hn + h) * Tn + t) * Dn + d0;
        float4 w0, w1;
        w0.x = o[0]; w0.y = o[1]; w0.z = o[2]; w0.w = o[3];
        w1.x = o[4]; w1.y = o[5]; w1.z = o[6]; w1.w = o[7];
        *(float4*)&dst[base]     = w0;
        *(float4*)&dst[base + 4] = w1;
    }
}

// ============================================================================
// Kernel 2: causal flash attention, packed f32x2 math (FFMA2).
// 128 q-rows/block (1/thread). KV tiles via cp.async DOUBLE-BUFFER (32 KB
// static smem, no persistent prefetch registers). Causal tile skipping.
// ============================================================================
__global__ __launch_bounds__(128) void attn_kernel()
{
    __shared__ float Ks[2][32 * 64];
    __shared__ float Vs[2][32 * 64];

    const int tid = threadIdx.x;
    const int qb = blockIdx.x;
    const int bh = blockIdx.y;
    const int q0 = qb * 128;

    const float* __restrict__ qptr = g_q + (size_t)bh * Tn * Dn;
    const float* __restrict__ kptr = g_k + (size_t)bh * Tn * Dn;
    const float* __restrict__ vptr = g_v + (size_t)bh * Tn * Dn;

    const uint32_t ks_s = (uint32_t)__cvta_generic_to_shared(&Ks[0][0]);
    const uint32_t vs_s = (uint32_t)__cvta_generic_to_shared(&Vs[0][0]);

    // Q row -> 32 packed pairs, pre-scaled by 1/sqrt(D)
    u64t qp[32];
    {
        const u64t sc2 = pack2(0.125f, 0.125f);
        const ulonglong2* qrow = (const ulonglong2*)&qptr[(size_t)(q0 + tid) * Dn];
        #pragma unroll
        for (int i = 0; i < 16; i++) {
            ulonglong2 qq = qrow[i];
            qp[2 * i + 0] = mul2(qq.x, sc2);
            qp[2 * i + 1] = mul2(qq.y, sc2);
        }
    }

    const int t_q = q0 + tid;
    float m_run = -1e30f, l_run = 0.f;
    u64t accp[32];
    #pragma unroll
    for (int i = 0; i < 32; i++) accp[i] = 0ull;

    const int ntiles = (q0 + 128) / 32;   // causal skip (>= 4)

    // issue tile kt's loads into buffer kt&1
    auto issue_tile = [&](int kt) {
        const int base_r = kt * 32;
        const uint32_t soff = (uint32_t)((kt & 1) * 32 * 64 * 4);
        #pragma unroll
        for (int u = 0; u < 4; u++) {
            const int idx = tid + u * 128;
            const int r = idx >> 4, c = (idx & 15) * 4;
            const uint32_t so = soff + (uint32_t)(r * 64 + c) * 4;
            cpa16(ks_s + so, &kptr[(base_r + r) * Dn + c]);
            cpa16(vs_s + so, &vptr[(base_r + r) * Dn + c]);
        }
        cpa_commit();
    };

    issue_tile(0);

    for (int kt = 0; kt < ntiles; kt++) {
        if (kt + 1 < ntiles) { issue_tile(kt + 1); cpa_wait1(); }
        else                 { cpa_wait0(); }
        __syncthreads();                      // tile kt visible to all threads

        const float* __restrict__ Kb = &Ks[kt & 1][0];
        const float* __restrict__ Vb = &Vs[kt & 1][0];
        const int kbase = kt * 32;

        // --- scores: packed dot products ---
        float sreg[32];
        float tmax = -1e30f;
        #pragma unroll
        for (int j = 0; j < 32; j += 4) {
            u64t a0 = 0ull, a1 = 0ull, a2 = 0ull, a3 = 0ull;
            #pragma unroll
            for (int d = 0; d < 64; d += 4) {
                const int pi = d >> 1;
                ulonglong2 k0 = *(const ulonglong2*)&Kb[(j + 0) * 64 + d];
                ulonglong2 k1 = *(const ulonglong2*)&Kb[(j + 1) * 64 + d];
                ulonglong2 k2 = *(const ulonglong2*)&Kb[(j + 2) * 64 + d];
                ulonglong2 k3 = *(const ulonglong2*)&Kb[(j + 3) * 64 + d];
                a0 = fma2(qp[pi], k0.x, a0); a0 = fma2(qp[pi + 1], k0.y, a0);
                a1 = fma2(qp[pi], k1.x, a1); a1 = fma2(qp[pi + 1], k1.y, a1);
                a2 = fma2(qp[pi], k2.x, a2); a2 = fma2(qp[pi + 1], k2.y, a2);
                a3 = fma2(qp[pi], k3.x, a3); a3 = fma2(qp[pi + 1], k3.y, a3);
            }
            float2 f0 = unpack2(a0), f1 = unpack2(a1), f2 = unpack2(a2), f3 = unpack2(a3);
            float s0 = f0.x + f0.y, s1 = f1.x + f1.y, s2 = f2.x + f2.y, s3 = f3.x + f3.y;
            if (kbase + j + 0 > t_q) s0 = -1e30f;
            if (kbase + j + 1 > t_q) s1 = -1e30f;
            if (kbase + j + 2 > t_q) s2 = -1e30f;
            if (kbase + j + 3 > t_q) s3 = -1e30f;
            sreg[j + 0] = s0; sreg[j + 1] = s1;
            sreg[j + 2] = s2; sreg[j + 3] = s3;
            tmax = fmaxf(tmax, fmaxf(fmaxf(s0, s1), fmaxf(s2, s3)));
        }

        // --- online softmax update ---
        const float m_new = fmaxf(m_run, tmax);
        const float corr = __expf(m_run - m_new);
        const u64t corr2 = pack2(corr, corr);
        l_run *= corr;
        #pragma unroll
        for (int i = 0; i < 32; i++) accp[i] = mul2(accp[i], corr2);
        m_run = m_new;

        float lsum = 0.f;
        #pragma unroll
        for (int j = 0; j < 32; j += 4) {
            float p0 = __expf(sreg[j + 0] - m_new);
            float p1 = __expf(sreg[j + 1] - m_new);
            float p2 = __expf(sreg[j + 2] - m_new);
            float p3 = __expf(sreg[j + 3] - m_new);
            lsum += (p0 + p1) + (p2 + p3);
            const u64t pj0 = pack2(p0, p0), pj1 = pack2(p1, p1);
            const u64t pj2 = pack2(p2, p2), pj3 = pack2(p3, p3);
            #pragma unroll
            for (int d = 0; d < 64; d += 4) {
                const int pi = d >> 1;
                ulonglong2 v0 = *(const ulonglong2*)&Vb[(j + 0) * 64 + d];
                ulonglong2 v1 = *(const ulonglong2*)&Vb[(j + 1) * 64 + d];
                ulonglong2 v2 = *(const ulonglong2*)&Vb[(j + 2) * 64 + d];
                ulonglong2 v3 = *(const ulonglong2*)&Vb[(j + 3) * 64 + d];
                accp[pi]     = fma2(pj3, v3.x, fma2(pj2, v2.x, fma2(pj1, v1.x, fma2(pj0, v0.x, accp[pi]))));
                accp[pi + 1] = fma2(pj3, v3.y, fma2(pj2, v2.y, fma2(pj1, v1.y, fma2(pj0, v0.y, accp[pi + 1]))));
            }
        }
        l_run += lsum;

        __syncthreads();   // all threads done with buffer kt&1 before it is re-filled
    }

    const float inv = 1.f / l_run;
    const u64t inv2 = pack2(inv, inv);
    const int bb = bh / Hn, h = bh % Hn;
    float* outp = g_att + ((size_t)(bb * Tn + t_q)) * Cn + h * Dn;
    #pragma unroll
    for (int i = 0; i < 32; i += 2) {
        ulonglong2 o;
        o.x = mul2(accp[i],     inv2);
        o.y = mul2(accp[i + 1], inv2);
        *(ulonglong2*)&outp[i * 2] = o;
    }
}

// ============================================================================
// Kernel 3: out = g_att @ w_proj^T — same 128x128x16 / packed 8x8 scheme
// ============================================================================
__global__ __launch_bounds__(256) void proj_kernel(
    const float* __restrict__ wp, float* __restrict__ out)
{
    __shared__ float As[16][SMP];
    __shared__ float Bs[16][SMP];

    const int tid = threadIdx.x;
    const int tx = tid & 15;
    const int ty = tid >> 4;
    const int m0 = blockIdx.y * 128;
    const int n0 = blockIdx.x * 128;

    u64t accp[8][4];
    #pragma unroll
    for (int i = 0; i < 8; i++)
        #pragma unroll
        for (int j = 0; j < 4; j++) accp[i][j] = 0ull;

    for (int k0 = 0; k0 < Cn; k0 += 16) {
        #pragma unroll
        for (int u = 0; u < 2; u++) {
            const int idx = tid + u * 256;
            const int r = idx >> 2, c4 = (idx & 3) * 4;
            float4 a = *(const float4*)&g_att[(m0 + r) * Cn + k0 + c4];
            float4 b = *(const float4*)&wp[(n0 + r) * Cn + k0 + c4];
            As[c4 + 0][r] = a.x; As[c4 + 1][r] = a.y;
            As[c4 + 2][r] = a.z; As[c4 + 3][r] = a.w;
            Bs[c4 + 0][r] = b.x; Bs[c4 + 1][r] = b.y;
            Bs[c4 + 2][r] = b.z; Bs[c4 + 3][r] = b.w;
        }
        __syncthreads();
        #pragma unroll
        for (int kk = 0; kk < 16; kk++) {
            float4 a0 = *(const float4*)&As[kk][ty * 8];
            float4 a1 = *(const float4*)&As[kk][ty * 8 + 4];
            ulonglong2 b01 = *(const ulonglong2*)&Bs[kk][tx * 8];
            ulonglong2 b23 = *(const ulonglong2*)&Bs[kk][tx * 8 + 4];
            const u64t bp0 = b01.x, bp1 = b01.y, bp2 = b23.x, bp3 = b23.y;
            float ar[8] = {a0.x, a0.y, a0.z, a0.w, a1.x, a1.y, a1.z, a1.w};
            #pragma unroll
            for (int i = 0; i < 8; i++) {
                const u64t ai = pack2(ar[i], ar[i]);
                accp[i][0] = fma2(ai, bp0, accp[i][0]);
                accp[i][1] = fma2(ai, bp1, accp[i][1]);
                accp[i][2] = fma2(ai, bp2, accp[i][2]);
                accp[i][3] = fma2(ai, bp3, accp[i][3]);
            }
        }
        __syncthreads();
    }

    #pragma unroll
    for (int i = 0; i < 8; i++) {
        const int m = m0 + ty * 8 + i;
        const int n = n0 + tx * 8;
        ulonglong2 w0, w1;
        w0.x = accp[i][0]; w0.y = accp[i][1];
        w1.x = accp[i][2]; w1.y = accp[i][3];
        *(ulonglong2*)&out[m * Cn + n]     = w0;
        *(ulonglong2*)&out[m * Cn + n + 4] = w1;
    }
}

// ============================================================================
extern "C" void kernel_launch(void* const* d_in, const int* in_sizes, int n_in,
                              void* d_out, int out_size)
{
    const float* x      = (const float*)d_in[0];
    const float* w_qkv  = (const float*)d_in[1];
    const float* w_proj = (const float*)d_in[2];
    const float* r_sin  = (const float*)d_in[3];
    const float* r_cos  = (const float*)d_in[4];
    float* out = (float*)d_out;

    // kernel 1: qkv + rope (packed f32x2)
    {
        dim3 grid(N_QKV / 128, Mrows / 128);
        qkv_rope_kernel<<<grid, 256>>>(x, w_qkv, r_sin, r_cos);
    }

    // kernel 2: attention (packed f32x2 + cp.async double buffer)
    {
        dim3 grid(Tn / 128, Bn * Hn);
        attn_kernel<<<grid, 128>>>();
    }

    // kernel 3: output projection (packed f32x2)
    {
        dim3 grid(Cn / 128, Mrows / 128);
        proj_kernel<<<grid, 256>>>(w_proj, out);
    }
}

// round 14
// speedup vs baseline: 1.7634x; 1.1737x over previous
#include <cuda_runtime.h>
#include <cstdint>

#define Bn 4
#define Tn 2048
#define Cn 768
#define Hn 12
#define Dn 64
#define Mrows (Bn * Tn)   // 8192
#define N_QKV (3 * Cn)    // 2304
#define NQB (Tn / 128)    // 16 q-blocks per (b,h)
#define NBH (Bn * Hn)     // 48

// ---- scratch (no allocs allowed) ----
__device__ float g_q[Bn * Hn * Tn * Dn];
__device__ float g_k[Bn * Hn * Tn * Dn];
__device__ float g_v[Bn * Hn * Tn * Dn];
__device__ float g_att[Bn * Tn * Cn];

#define SMP 132   // smem row stride: multiple of 4 floats -> 16B-aligned rows for LDS.128

// ---- packed fp32x2 helpers (sm_103a FFMA2 path; bit-exact per lane) ----
typedef unsigned long long u64t;
__device__ __forceinline__ u64t fma2(u64t a, u64t b, u64t c) {
    u64t r; asm("fma.rn.f32x2 %0, %1, %2, %3;" : "=l"(r) : "l"(a), "l"(b), "l"(c)); return r;
}
__device__ __forceinline__ u64t mul2(u64t a, u64t b) {
    u64t r; asm("mul.rn.f32x2 %0, %1, %2;" : "=l"(r) : "l"(a), "l"(b)); return r;
}
__device__ __forceinline__ u64t pack2(float lo, float hi) {
    u64t r; asm("mov.b64 %0, {%1, %2};" : "=l"(r) : "f"(lo), "f"(hi)); return r;
}
__device__ __forceinline__ float2 unpack2(u64t v) {
    float lo, hi; asm("mov.b64 {%0, %1}, %2;" : "=f"(lo), "=f"(hi) : "l"(v));
    return make_float2(lo, hi);
}

// ---- cp.async helpers (16B, L1-bypass) ----
__device__ __forceinline__ void cpa16(uint32_t saddr, const void* gaddr) {
    asm volatile("cp.async.cg.shared.global [%0], [%1], 16;" :: "r"(saddr), "l"(gaddr));
}
__device__ __forceinline__ void cpa_commit() {
    asm volatile("cp.async.commit_group;");
}
__device__ __forceinline__ void cpa_wait1() {
    asm volatile("cp.async.wait_group 1;");
}
__device__ __forceinline__ void cpa_wait0() {
    asm volatile("cp.async.wait_group 0;");
}

// ============================================================================
// Kernel 1: qkv = x @ w_qkv^T, fused RoPE, scatter to [b,h,t,d]
// 128x128x16 tile, 256 threads, 8x8 micro-tile on packed f32x2 (32 FFMA2/kk).
// ============================================================================
__global__ __launch_bounds__(256) void qkv_rope_kernel(
    const float* __restrict__ x, const float* __restrict__ w,
    const float* __restrict__ rsin, const float* __restrict__ rcos)
{
    __shared__ float As[16][SMP];
    __shared__ float Bs[16][SMP];

    const int tid = threadIdx.x;
    const int tx = tid & 15;
    const int ty = tid >> 4;
    const int m0 = blockIdx.y * 128;
    const int n0 = blockIdx.x * 128;

    u64t accp[8][4];
    #pragma unroll
    for (int i = 0; i < 8; i++)
        #pragma unroll
        for (int j = 0; j < 4; j++) accp[i][j] = 0ull;

    for (int k0 = 0; k0 < Cn; k0 += 16) {
        #pragma unroll
        for (int u = 0; u < 2; u++) {
            const int idx = tid + u * 256;
            const int r = idx >> 2, c4 = (idx & 3) * 4;
            float4 a = *(const float4*)&x[(m0 + r) * Cn + k0 + c4];
            float4 b = *(const float4*)&w[(n0 + r) * Cn + k0 + c4];
            As[c4 + 0][r] = a.x; As[c4 + 1][r] = a.y;
            As[c4 + 2][r] = a.z; As[c4 + 3][r] = a.w;
            Bs[c4 + 0][r] = b.x; Bs[c4 + 1][r] = b.y;
            Bs[c4 + 2][r] = b.z; Bs[c4 + 3][r] = b.w;
        }
        __syncthreads();
        #pragma unroll
        for (int kk = 0; kk < 16; kk++) {
            float4 a0 = *(const float4*)&As[kk][ty * 8];
            float4 a1 = *(const float4*)&As[kk][ty * 8 + 4];
            ulonglong2 b01 = *(const ulonglong2*)&Bs[kk][tx * 8];
            ulonglong2 b23 = *(const ulonglong2*)&Bs[kk][tx * 8 + 4];
            const u64t bp0 = b01.x, bp1 = b01.y, bp2 = b23.x, bp3 = b23.y;
            float ar[8] = {a0.x, a0.y, a0.z, a0.w, a1.x, a1.y, a1.z, a1.w};
            #pragma unroll
            for (int i = 0; i < 8; i++) {
                const u64t ai = pack2(ar[i], ar[i]);
                accp[i][0] = fma2(ai, bp0, accp[i][0]);
                accp[i][1] = fma2(ai, bp1, accp[i][1]);
                accp[i][2] = fma2(ai, bp2, accp[i][2]);
                accp[i][3] = fma2(ai, bp3, accp[i][3]);
            }
        }
        __syncthreads();
    }

    const int nbase = n0 + tx * 8;
    const int s   = nbase / Cn;
    const int rem = nbase % Cn;
    const int h   = rem / Dn;
    const int d0  = rem % Dn;

    #pragma unroll
    for (int i = 0; i < 8; i++) {
        const int m = m0 + ty * 8 + i;
        const int bb = m / Tn, t = m % Tn;
        float2 p0 = unpack2(accp[i][0]), p1 = unpack2(accp[i][1]);
        float2 p2 = unpack2(accp[i][2]), p3 = unpack2(accp[i][3]);
        float acc8[8] = {p0.x, p0.y, p1.x, p1.y, p2.x, p2.y, p3.x, p3.y};
        float* __restrict__ dst;
        float o[8];
        if (s == 2) {
            dst = g_v;
            #pragma unroll
            for (int j = 0; j < 8; j++) o[j] = acc8[j];
        } else {
            dst = (s == 0) ? g_q : g_k;
            const int i0 = d0 >> 1;
            #pragma unroll
            for (int p = 0; p < 4; p++) {
                float sp = rsin[t * (Dn / 2) + i0 + p];
                float cp = rcos[t * (Dn / 2) + i0 + p];
                float e = acc8[2 * p], f = acc8[2 * p + 1];
                o[2 * p]     = e * cp - f * sp;
                o[2 * p + 1] = e * sp + f * cp;
            }
        }
        const int base = ((bb * Hn + h) * Tn + t) * Dn + d0;
        float4 w0, w1;
        w0.x = o[0]; w0.y = o[1]; w0.z = o[2]; w0.w = o[3];
        w1.x = o[4]; w1.y = o[5]; w1.z = o[6]; w1.w = o[7];
        *(float4*)&dst[base]     = w0;
        *(float4*)&dst[base + 4] = w1;
    }
}

// ============================================================================
// Kernel 2: causal flash attention, packed f32x2 math (FFMA2).
// 1-D grid with LPT ordering: heaviest q-blocks (most causal tiles) launch
// first so the drain wave holds only light blocks. Work per block unchanged.
// ============================================================================
__global__ __launch_bounds__(128) void attn_kernel()
{
    __shared__ float Ks[2][32 * 64];
    __shared__ float Vs[2][32 * 64];

    const int tid = threadIdx.x;
    // LPT mapping: bid 0..47 -> qb=15 (64 tiles), bid 48..95 -> qb=14, ...
    const int bid = blockIdx.x;
    const int qb = (NQB - 1) - (bid / NBH);
    const int bh = bid % NBH;
    const int q0 = qb * 128;

    const float* __restrict__ qptr = g_q + (size_t)bh * Tn * Dn;
    const float* __restrict__ kptr = g_k + (size_t)bh * Tn * Dn;
    const float* __restrict__ vptr = g_v + (size_t)bh * Tn * Dn;

    const uint32_t ks_s = (uint32_t)__cvta_generic_to_shared(&Ks[0][0]);
    const uint32_t vs_s = (uint32_t)__cvta_generic_to_shared(&Vs[0][0]);

    // Q row -> 32 packed pairs, pre-scaled by 1/sqrt(D)
    u64t qp[32];
    {
        const u64t sc2 = pack2(0.125f, 0.125f);
        const ulonglong2* qrow = (const ulonglong2*)&qptr[(size_t)(q0 + tid) * Dn];
        #pragma unroll
        for (int i = 0; i < 16; i++) {
            ulonglong2 qq = qrow[i];
            qp[2 * i + 0] = mul2(qq.x, sc2);
            qp[2 * i + 1] = mul2(qq.y, sc2);
        }
    }

    const int t_q = q0 + tid;
    float m_run = -1e30f, l_run = 0.f;
    u64t accp[32];
    #pragma unroll
    for (int i = 0; i < 32; i++) accp[i] = 0ull;

    const int ntiles = (q0 + 128) / 32;   // causal skip (>= 4)

    // issue tile kt's loads into buffer kt&1
    auto issue_tile = [&](int kt) {
        const int base_r = kt * 32;
        const uint32_t soff = (uint32_t)((kt & 1) * 32 * 64 * 4);
        #pragma unroll
        for (int u = 0; u < 4; u++) {
            const int idx = tid + u * 128;
            const int r = idx >> 4, c = (idx & 15) * 4;
            const uint32_t so = soff + (uint32_t)(r * 64 + c) * 4;
            cpa16(ks_s + so, &kptr[(base_r + r) * Dn + c]);
            cpa16(vs_s + so, &vptr[(base_r + r) * Dn + c]);
        }
        cpa_commit();
    };

    issue_tile(0);

    for (int kt = 0; kt < ntiles; kt++) {
        if (kt + 1 < ntiles) { issue_tile(kt + 1); cpa_wait1(); }
        else                 { cpa_wait0(); }
        __syncthreads();                      // tile kt visible to all threads

        const float* __restrict__ Kb = &Ks[kt & 1][0];
        const float* __restrict__ Vb = &Vs[kt & 1][0];
        const int kbase = kt * 32;

        // --- scores: packed dot products ---
        float sreg[32];
        float tmax = -1e30f;
        #pragma unroll
        for (int j = 0; j < 32; j += 4) {
            u64t a0 = 0ull, a1 = 0ull, a2 = 0ull, a3 = 0ull;
            #pragma unroll
            for (int d = 0; d < 64; d += 4) {
                const int pi = d >> 1;
                ulonglong2 k0 = *(const ulonglong2*)&Kb[(j + 0) * 64 + d];
                ulonglong2 k1 = *(const ulonglong2*)&Kb[(j + 1) * 64 + d];
                ulonglong2 k2 = *(const ulonglong2*)&Kb[(j + 2) * 64 + d];
                ulonglong2 k3 = *(const ulonglong2*)&Kb[(j + 3) * 64 + d];
                a0 = fma2(qp[pi], k0.x, a0); a0 = fma2(qp[pi + 1], k0.y, a0);
                a1 = fma2(qp[pi], k1.x, a1); a1 = fma2(qp[pi + 1], k1.y, a1);
                a2 = fma2(qp[pi], k2.x, a2); a2 = fma2(qp[pi + 1], k2.y, a2);
                a3 = fma2(qp[pi], k3.x, a3); a3 = fma2(qp[pi + 1], k3.y, a3);
            }
            float2 f0 = unpack2(a0), f1 = unpack2(a1), f2 = unpack2(a2), f3 = unpack2(a3);
            float s0 = f0.x + f0.y, s1 = f1.x + f1.y, s2 = f2.x + f2.y, s3 = f3.x + f3.y;
            if (kbase + j + 0 > t_q) s0 = -1e30f;
            if (kbase + j + 1 > t_q) s1 = -1e30f;
            if (kbase + j + 2 > t_q) s2 = -1e30f;
            if (kbase + j + 3 > t_q) s3 = -1e30f;
            sreg[j + 0] = s0; sreg[j + 1] = s1;
            sreg[j + 2] = s2; sreg[j + 3] = s3;
            tmax = fmaxf(tmax, fmaxf(fmaxf(s0, s1), fmaxf(s2, s3)));
        }

        // --- online softmax update ---
        const float m_new = fmaxf(m_run, tmax);
        const float corr = __expf(m_run - m_new);
        const u64t corr2 = pack2(corr, corr);
        l_run *= corr;
        #pragma unroll
        for (int i = 0; i < 32; i++) accp[i] = mul2(accp[i], corr2);
        m_run = m_new;

        float lsum = 0.f;
        #pragma unroll
        for (int j = 0; j < 32; j += 4) {
            float p0 = __expf(sreg[j + 0] - m_new);
            float p1 = __expf(sreg[j + 1] - m_new);
            float p2 = __expf(sreg[j + 2] - m_new);
            float p3 = __expf(sreg[j + 3] - m_new);
            lsum += (p0 + p1) + (p2 + p3);
            const u64t pj0 = pack2(p0, p0), pj1 = pack2(p1, p1);
            const u64t pj2 = pack2(p2, p2), pj3 = pack2(p3, p3);
            #pragma unroll
            for (int d = 0; d < 64; d += 4) {
                const int pi = d >> 1;
                ulonglong2 v0 = *(const ulonglong2*)&Vb[(j + 0) * 64 + d];
                ulonglong2 v1 = *(const ulonglong2*)&Vb[(j + 1) * 64 + d];
                ulonglong2 v2 = *(const ulonglong2*)&Vb[(j + 2) * 64 + d];
                ulonglong2 v3 = *(const ulonglong2*)&Vb[(j + 3) * 64 + d];
                accp[pi]     = fma2(pj3, v3.x, fma2(pj2, v2.x, fma2(pj1, v1.x, fma2(pj0, v0.x, accp[pi]))));
                accp[pi + 1] = fma2(pj3, v3.y, fma2(pj2, v2.y, fma2(pj1, v1.y, fma2(pj0, v0.y, accp[pi + 1]))));
            }
        }
        l_run += lsum;

        __syncthreads();   // all threads done with buffer kt&1 before it is re-filled
    }

    const float inv = 1.f / l_run;
    const u64t inv2 = pack2(inv, inv);
    const int bb = bh / Hn, h = bh % Hn;
    float* outp = g_att + ((size_t)(bb * Tn + t_q)) * Cn + h * Dn;
    #pragma unroll
    for (int i = 0; i < 32; i += 2) {
        ulonglong2 o;
        o.x = mul2(accp[i],     inv2);
        o.y = mul2(accp[i + 1], inv2);
        *(ulonglong2*)&outp[i * 2] = o;
    }
}

// ============================================================================
// Kernel 3: out = g_att @ w_proj^T — same 128x128x16 / packed 8x8 scheme
// ============================================================================
__global__ __launch_bounds__(256) void proj_kernel(
    const float* __restrict__ wp, float* __restrict__ out)
{
    __shared__ float As[16][SMP];
    __shared__ float Bs[16][SMP];

    const int tid = threadIdx.x;
    const int tx = tid & 15;
    const int ty = tid >> 4;
    const int m0 = blockIdx.y * 128;
    const int n0 = blockIdx.x * 128;

    u64t accp[8][4];
    #pragma unroll
    for (int i = 0; i < 8; i++)
        #pragma unroll
        for (int j = 0; j < 4; j++) accp[i][j] = 0ull;

    for (int k0 = 0; k0 < Cn; k0 += 16) {
        #pragma unroll
        for (int u = 0; u < 2; u++) {
            const int idx = tid + u * 256;
            const int r = idx >> 2, c4 = (idx & 3) * 4;
            float4 a = *(const float4*)&g_att[(m0 + r) * Cn + k0 + c4];
            float4 b = *(const float4*)&wp[(n0 + r) * Cn + k0 + c4];
            As[c4 + 0][r] = a.x; As[c4 + 1][r] = a.y;
            As[c4 + 2][r] = a.z; As[c4 + 3][r] = a.w;
            Bs[c4 + 0][r] = b.x; Bs[c4 + 1][r] = b.y;
            Bs[c4 + 2][r] = b.z; Bs[c4 + 3][r] = b.w;
        }
        __syncthreads();
        #pragma unroll
        for (int kk = 0; kk < 16; kk++) {
            float4 a0 = *(const float4*)&As[kk][ty * 8];
            float4 a1 = *(const float4*)&As[kk][ty * 8 + 4];
            ulonglong2 b01 = *(const ulonglong2*)&Bs[kk][tx * 8];
            ulonglong2 b23 = *(const ulonglong2*)&Bs[kk][tx * 8 + 4];
            const u64t bp0 = b01.x, bp1 = b01.y, bp2 = b23.x, bp3 = b23.y;
            float ar[8] = {a0.x, a0.y, a0.z, a0.w, a1.x, a1.y, a1.z, a1.w};
            #pragma unroll
            for (int i = 0; i < 8; i++) {
                const u64t ai = pack2(ar[i], ar[i]);
                accp[i][0] = fma2(ai, bp0, accp[i][0]);
                accp[i][1] = fma2(ai, bp1, accp[i][1]);
                accp[i][2] = fma2(ai, bp2, accp[i][2]);
                accp[i][3] = fma2(ai, bp3, accp[i][3]);
            }
        }
        __syncthreads();
    }

    #pragma unroll
    for (int i = 0; i < 8; i++) {
        const int m = m0 + ty * 8 + i;
        const int n = n0 + tx * 8;
        ulonglong2 w0, w1;
        w0.x = accp[i][0]; w0.y = accp[i][1];
        w1.x = accp[i][2]; w1.y = accp[i][3];
        *(ulonglong2*)&out[m * Cn + n]     = w0;
        *(ulonglong2*)&out[m * Cn + n + 4] = w1;
    }
}

// ============================================================================
extern "C" void kernel_launch(void* const* d_in, const int* in_sizes, int n_in,
                              void* d_out, int out_size)
{
    const float* x      = (const float*)d_in[0];
    const float* w_qkv  = (const float*)d_in[1];
    const float* w_proj = (const float*)d_in[2];
    const float* r_sin  = (const float*)d_in[3];
    const float* r_cos  = (const float*)d_in[4];
    float* out = (float*)d_out;

    // kernel 1: qkv + rope (packed f32x2)
    {
        dim3 grid(N_QKV / 128, Mrows / 128);
        qkv_rope_kernel<<<grid, 256>>>(x, w_qkv, r_sin, r_cos);
    }

    // kernel 2: attention (packed f32x2, LPT-ordered 1-D grid)
    {
        attn_kernel<<<NQB * NBH, 128>>>();
    }

    // kernel 3: output projection (packed f32x2)
    {
        dim3 grid(Cn / 128, Mrows / 128);
        proj_kernel<<<grid, 256>>>(w_proj, out);
    }
}